// round 6
// baseline (speedup 1.0000x reference)
#include <cuda_runtime.h>
#include <cuda_bf16.h>
#include <cstdint>

#define D       128
#define NREL    48
#define NB      8
#define NENT    50000
#define NSPEC   64
#define NEDGE   600000
#define KACC    1024
#define KTOT    1152
#define MTILE   128
#define NTIL    391                 // ceil(50000/128)
#define MPAD    (NTIL * MTILE)      // 50048
#define KC      16
#define NCH     (KTOT / KC)         // 72
#define SSTR    24                  // smem row stride (bf16): 48 B, LDSM conflict-free

// ---------------- device scratch ----------------
__device__ int   g_deg[NENT];
__device__ int   g_off[NENT];
__device__ int   g_cur[NENT];
__device__ int   g_total;
__device__ int   g_pk[NEDGE];
__device__ __nv_bfloat16 g_Ahi[(size_t)MPAD * KTOT];   // pad rows stay zero
__device__ __nv_bfloat16 g_Alo[(size_t)MPAD * KTOT];
__device__ __nv_bfloat16 g_Bhi[(size_t)D * KTOT];      // B^T [n][k]
__device__ __nv_bfloat16 g_Blo[(size_t)D * KTOT];

__device__ __forceinline__ int clampi(int v, int lo, int hi) {
    return v < lo ? lo : (v > hi ? hi : v);
}
__device__ __forceinline__ uint32_t smem_u32(const void* p) {
    uint32_t a;
    asm("{ .reg .u64 t; cvta.to.shared.u64 t, %1; cvt.u32.u64 %0, t; }"
        : "=r"(a) : "l"(p));
    return a;
}
__device__ __forceinline__ void ldsm4(uint32_t* r, uint32_t addr) {
    asm volatile("ldmatrix.sync.aligned.m8n8.x4.shared.b16 {%0,%1,%2,%3}, [%4];"
        : "=r"(r[0]), "=r"(r[1]), "=r"(r[2]), "=r"(r[3]) : "r"(addr));
}
__device__ __forceinline__ void mma_bf16(float* c, const uint32_t* a,
                                         const uint32_t* b) {
    asm volatile(
        "mma.sync.aligned.m16n8k16.row.col.f32.bf16.bf16.f32 "
        "{%0,%1,%2,%3}, {%4,%5,%6,%7}, {%8,%9}, {%0,%1,%2,%3};"
        : "+f"(c[0]), "+f"(c[1]), "+f"(c[2]), "+f"(c[3])
        : "r"(a[0]), "r"(a[1]), "r"(a[2]), "r"(a[3]), "r"(b[0]), "r"(b[1]));
}
__device__ __forceinline__ void cp16(uint32_t dst, const void* src) {
    asm volatile("cp.async.cg.shared.global [%0], [%1], 16;"
                 :: "r"(dst), "l"(src) : "memory");
}
__device__ __forceinline__ void cp_commit() {
    asm volatile("cp.async.commit_group;" ::: "memory");
}
template <int N>
__device__ __forceinline__ void cp_wait() {
    asm volatile("cp.async.wait_group %0;" :: "n"(N) : "memory");
}

// bf16 two-term split of a float4, packed stores
__device__ __forceinline__ void split_store4(__nv_bfloat16* hi, __nv_bfloat16* lo,
                                             float4 v) {
    __nv_bfloat16 h0 = __float2bfloat16(v.x), h1 = __float2bfloat16(v.y);
    __nv_bfloat16 h2 = __float2bfloat16(v.z), h3 = __float2bfloat16(v.w);
    __nv_bfloat16 l0 = __float2bfloat16(v.x - __bfloat162float(h0));
    __nv_bfloat16 l1 = __float2bfloat16(v.y - __bfloat162float(h1));
    __nv_bfloat16 l2 = __float2bfloat16(v.z - __bfloat162float(h2));
    __nv_bfloat16 l3 = __float2bfloat16(v.w - __bfloat162float(h3));
    union { __nv_bfloat16 b[4]; uint2 u; } H, L;
    H.b[0] = h0; H.b[1] = h1; H.b[2] = h2; H.b[3] = h3;
    L.b[0] = l0; L.b[1] = l1; L.b[2] = l2; L.b[3] = l3;
    *(uint2*)hi = H.u;
    *(uint2*)lo = L.u;
}

// ---------------- preprocessing ----------------
__global__ void k_zero() {
    int total = NENT + 1;
    for (int i = blockIdx.x * blockDim.x + threadIdx.x; i < total;
         i += gridDim.x * blockDim.x) {
        if (i < NENT) g_deg[i] = 0;
        else          g_total = 0;
    }
}

__global__ void k_count(const int* __restrict__ ei) {
    int e = blockIdx.x * blockDim.x + threadIdx.x;
    if (e >= NEDGE) return;
    int dst = clampi(ei[NEDGE + e], 0, NENT - 1);
    atomicAdd(&g_deg[dst], 1);
}

// segment offsets: warp scan + one atomic per warp (order-free, disjoint)
__global__ void k_off() {
    int n = blockIdx.x * blockDim.x + threadIdx.x;
    int lane = threadIdx.x & 31;
    int deg = (n < NENT) ? g_deg[n] : 0;
    int incl = deg;
#pragma unroll
    for (int o = 1; o < 32; o <<= 1) {
        int t = __shfl_up_sync(0xFFFFFFFFu, incl, o);
        if (lane >= o) incl += t;
    }
    int tot = __shfl_sync(0xFFFFFFFFu, incl, 31);
    int base = 0;
    if (lane == 31) base = atomicAdd(&g_total, tot);
    base = __shfl_sync(0xFFFFFFFFu, base, 31);
    if (n < NENT) {
        int st = base + incl - deg;
        g_off[n] = st;
        g_cur[n] = st;
    }
}

__global__ void k_scatter(const int* __restrict__ ei, const int* __restrict__ et) {
    int e = blockIdx.x * blockDim.x + threadIdx.x;
    if (e >= NEDGE) return;
    int src = clampi(ei[e], 0, NENT - 1);
    int dst = clampi(ei[NEDGE + e], 0, NENT - 1);
    int typ = clampi(et[e], 0, NREL - 1);
    int pos = atomicAdd(&g_cur[dst], 1);
    if (pos >= NEDGE) return;
    g_pk[pos] = src | (typ << 16);
}

// ---------------- aggregation: warp per node, local type-histogram -----------
__global__ __launch_bounds__(256)
void k_agg(const float* __restrict__ x, const float* __restrict__ comp) {
    __shared__ float comps[NREL * NB];
    __shared__ int   cnts[8][NREL];
    int tid = threadIdx.x;
    for (int t = tid; t < NREL * NB; t += 256) comps[t] = comp[t];
    __syncthreads();

    int w = tid >> 5, lane = tid & 31;
    int n = blockIdx.x * 8 + w;
    if (n >= NENT) return;

    // per-(type, dst=n) edge counts, local to this warp
    for (int t = lane; t < NREL; t += 32) cnts[w][t] = 0;
    __syncwarp();
    int s = g_off[n], e = s + g_deg[n];
    for (int idx = s + lane; idx < e; idx += 32)
        atomicAdd(&cnts[w][(g_pk[idx] >> 16) & 0x3F], 1);
    __syncwarp();

    float4 av[NB];
#pragma unroll
    for (int b = 0; b < NB; b++) av[b] = make_float4(0.f, 0.f, 0.f, 0.f);

    for (int idx = s; idx < e; idx++) {
        int pk  = g_pk[idx];
        int src = pk & 0xFFFF;
        int typ = (pk >> 16) & 0x3F;
        float nm = 1.0f / (float)cnts[w][typ];
        float4 xv = *((const float4*)(x + (size_t)src * D) + lane);
#pragma unroll
        for (int b = 0; b < NB; b++) {
            float c = comps[typ * NB + b] * nm;
            av[b].x += c * xv.x; av[b].y += c * xv.y;
            av[b].z += c * xv.z; av[b].w += c * xv.w;
        }
    }

    size_t rb = (size_t)n * KTOT;
#pragma unroll
    for (int b = 0; b < NB; b++)
        split_store4(g_Ahi + rb + b * D + lane * 4, g_Alo + rb + b * D + lane * 4, av[b]);
    float4 xv = *((const float4*)(x + (size_t)n * D) + lane);
    split_store4(g_Ahi + rb + KACC + lane * 4, g_Alo + rb + KACC + lane * 4, xv);
}

// ---------------- B^T hi/lo: g_B*[n][k] = [basis;root][k][n] ----------------
__global__ void k_prepB(const float* __restrict__ basis, const float* __restrict__ root) {
    int i = blockIdx.x * blockDim.x + threadIdx.x;
    if (i >= D * KTOT) return;
    int n = i / KTOT, k = i % KTOT;
    float v = (k < KACC) ? basis[(size_t)k * D + n] : root[(size_t)(k - KACC) * D + n];
    __nv_bfloat16 h = __float2bfloat16(v);
    g_Bhi[i] = h;
    g_Blo[i] = __float2bfloat16(v - __bfloat162float(h));
}

// ---------------- bf16 HMMA GEMM, cp.async double-buffered -------------------
// CTA: 128x128 C tile, 8 warps = 2(m) x 4(n), each warp 64x32. KC=16, 2 stages.
__global__ __launch_bounds__(256)
void k_gemm(const float* __restrict__ bias, float* __restrict__ out) {
    __shared__ __align__(16) __nv_bfloat16 sA[2][2][MTILE][SSTR];  // 24 KB
    __shared__ __align__(16) __nv_bfloat16 sB[2][2][D][SSTR];      // 24 KB

    int tid = threadIdx.x, wid = tid >> 5, lane = tid & 31;
    int m0 = blockIdx.x * MTILE;
    int wm = wid & 1;
    int wn = wid >> 1;

    int pr = tid >> 1, pq = tid & 1;   // prefetch row / 16B-chunk

    float c[4][4][4];
#pragma unroll
    for (int mt = 0; mt < 4; mt++)
#pragma unroll
        for (int nt = 0; nt < 4; nt++)
#pragma unroll
            for (int r = 0; r < 4; r++) c[mt][nt][r] = 0.f;

    // prologue: prefetch chunk 0
    {
        size_t ga = (size_t)(m0 + pr) * KTOT + pq * 8;
        size_t gb = (size_t)pr * KTOT + pq * 8;
        cp16(smem_u32(&sA[0][0][pr][pq * 8]), g_Ahi + ga);
        cp16(smem_u32(&sA[0][1][pr][pq * 8]), g_Alo + ga);
        cp16(smem_u32(&sB[0][0][pr][pq * 8]), g_Bhi + gb);
        cp16(smem_u32(&sB[0][1][pr][pq * 8]), g_Blo + gb);
        cp_commit();
    }

    for (int ch = 0; ch < NCH; ch++) {
        int st = ch & 1;
        if (ch + 1 < NCH) {
            int ns = (ch + 1) & 1;
            int kc = (ch + 1) * KC;
            size_t ga = (size_t)(m0 + pr) * KTOT + kc + pq * 8;
            size_t gb = (size_t)pr * KTOT + kc + pq * 8;
            cp16(smem_u32(&sA[ns][0][pr][pq * 8]), g_Ahi + ga);
            cp16(smem_u32(&sA[ns][1][pr][pq * 8]), g_Alo + ga);
            cp16(smem_u32(&sB[ns][0][pr][pq * 8]), g_Bhi + gb);
            cp16(smem_u32(&sB[ns][1][pr][pq * 8]), g_Blo + gb);
        }
        cp_commit();
        cp_wait<1>();
        __syncthreads();

        uint32_t ah[4][4], al[4][4], bh[2][4], bl[2][4];
        int arow = wm * 64 + (lane & 15);
        int acol = (lane >> 4) * 8;
#pragma unroll
        for (int mt = 0; mt < 4; mt++) {
            ldsm4(ah[mt], smem_u32(&sA[st][0][arow + mt * 16][acol]));
            ldsm4(al[mt], smem_u32(&sA[st][1][arow + mt * 16][acol]));
        }
        int brow = wn * 32 + (lane & 7) + ((lane >> 4) << 3);
        int bcol = ((lane >> 3) & 1) * 8;
#pragma unroll
        for (int p = 0; p < 2; p++) {
            ldsm4(bh[p], smem_u32(&sB[st][0][brow + p * 16][bcol]));
            ldsm4(bl[p], smem_u32(&sB[st][1][brow + p * 16][bcol]));
        }
#pragma unroll
        for (int mt = 0; mt < 4; mt++)
#pragma unroll
            for (int nt = 0; nt < 4; nt++) {
                const uint32_t* bhp = &bh[nt >> 1][(nt & 1) * 2];
                const uint32_t* blp = &bl[nt >> 1][(nt & 1) * 2];
                mma_bf16(c[mt][nt], ah[mt], bhp);
                mma_bf16(c[mt][nt], ah[mt], blp);
                mma_bf16(c[mt][nt], al[mt], bhp);
            }
        __syncthreads();
    }

    // epilogue
#pragma unroll
    for (int mt = 0; mt < 4; mt++) {
#pragma unroll
        for (int nt = 0; nt < 4; nt++) {
            int m = m0 + wm * 64 + mt * 16 + (lane >> 2);
            int n = wn * 32 + nt * 8 + (lane & 3) * 2;
            float b0 = __ldg(bias + n), b1 = __ldg(bias + n + 1);
            if (m < NENT) {
                float2 v = make_float2(c[mt][nt][0] + b0, c[mt][nt][1] + b1);
                *(float2*)(out + (size_t)m * D + n) = v;
            }
            if (m + 8 < NENT) {
                float2 v = make_float2(c[mt][nt][2] + b0, c[mt][nt][3] + b1);
                *(float2*)(out + (size_t)(m + 8) * D + n) = v;
            }
        }
    }
}

// ---------------- special embedding concat ----------------
__global__ void k_special(const float* __restrict__ sp, float* __restrict__ out) {
    int i = blockIdx.x * blockDim.x + threadIdx.x;
    if (i < NSPEC * D) out[(size_t)NENT * D + i] = sp[i];
}

// ---------------- launch ----------------
extern "C" void kernel_launch(void* const* d_in, const int* in_sizes, int n_in,
                              void* d_out, int out_size) {
    const int*   ei    = (const int*)d_in[0];
    const int*   et    = (const int*)d_in[1];
    const float* x     = (const float*)d_in[2];
    const float* basis = (const float*)d_in[3];
    const float* comp  = (const float*)d_in[4];
    const float* root  = (const float*)d_in[5];
    const float* bias  = (const float*)d_in[6];
    const float* spec  = (const float*)d_in[7];
    float*       out   = (float*)d_out;

    k_zero<<<64, 256>>>();
    k_count<<<(NEDGE + 255) / 256, 256>>>(ei);
    k_off<<<(NENT + 255) / 256, 256>>>();
    k_scatter<<<(NEDGE + 255) / 256, 256>>>(ei, et);
    k_agg<<<(NENT + 7) / 8, 256>>>(x, comp);
    k_prepB<<<(D * KTOT + 255) / 256, 256>>>(basis, root);
    k_gemm<<<NTIL, 256>>>(bias, out);
    k_special<<<(NSPEC * D + 255) / 256, 256>>>(spec, out);
}

// round 7
// speedup vs baseline: 1.1844x; 1.1844x over previous
#include <cuda_runtime.h>
#include <cstdint>

#define D       128
#define NREL    48
#define NB      8
#define NENT    50000
#define NSPEC   64
#define NEDGE   600000
#define KACC    1024
#define KTOT    1152
#define MTILE   128
#define NTIL    391                 // ceil(50000/128)
#define MPAD    (NTIL * MTILE)      // 50048
#define KC      16
#define NCH     (KTOT / KC)         // 72
#define SSTR    20                  // smem row stride (floats): conflict-free frags

// ---------------- device scratch ----------------
__device__ int   g_deg[NENT];
__device__ int   g_off[NENT];
__device__ int   g_cur[NENT];
__device__ int   g_total;
__device__ int   g_pk[NEDGE];
__device__ float g_A[(size_t)MPAD * KTOT];    // fp32 (tf32-rounded); pad rows stay 0
__device__ float g_Bt[(size_t)D * KTOT];      // B^T [n][k], tf32-rounded

__device__ __forceinline__ int clampi(int v, int lo, int hi) {
    return v < lo ? lo : (v > hi ? hi : v);
}
__device__ __forceinline__ uint32_t smem_u32(const void* p) {
    uint32_t a;
    asm("{ .reg .u64 t; cvta.to.shared.u64 t, %1; cvt.u32.u64 %0, t; }"
        : "=r"(a) : "l"(p));
    return a;
}
__device__ __forceinline__ float tf32r(float v) {
    uint32_t u;
    asm("cvt.rna.tf32.f32 %0, %1;" : "=r"(u) : "f"(v));
    return __uint_as_float(u);
}
__device__ __forceinline__ float4 tf32r4(float4 v) {
    return make_float4(tf32r(v.x), tf32r(v.y), tf32r(v.z), tf32r(v.w));
}
__device__ __forceinline__ void mma_tf32(float* c, const uint32_t* a,
                                         const uint32_t* b) {
    asm volatile(
        "mma.sync.aligned.m16n8k8.row.col.f32.tf32.tf32.f32 "
        "{%0,%1,%2,%3}, {%4,%5,%6,%7}, {%8,%9}, {%0,%1,%2,%3};"
        : "+f"(c[0]), "+f"(c[1]), "+f"(c[2]), "+f"(c[3])
        : "r"(a[0]), "r"(a[1]), "r"(a[2]), "r"(a[3]), "r"(b[0]), "r"(b[1]));
}
__device__ __forceinline__ void cp16(uint32_t dst, const void* src) {
    asm volatile("cp.async.cg.shared.global [%0], [%1], 16;"
                 :: "r"(dst), "l"(src) : "memory");
}
__device__ __forceinline__ void cp_commit() {
    asm volatile("cp.async.commit_group;" ::: "memory");
}
template <int N>
__device__ __forceinline__ void cp_wait() {
    asm volatile("cp.async.wait_group %0;" :: "n"(N) : "memory");
}

// ---------------- preprocessing ----------------
__global__ void k_zero() {
    int total = NENT + 1;
    for (int i = blockIdx.x * blockDim.x + threadIdx.x; i < total;
         i += gridDim.x * blockDim.x) {
        if (i < NENT) g_deg[i] = 0;
        else          g_total = 0;
    }
}

__global__ void k_count(const int* __restrict__ ei) {
    int e = blockIdx.x * blockDim.x + threadIdx.x;
    if (e >= NEDGE) return;
    int dst = clampi(ei[NEDGE + e], 0, NENT - 1);
    atomicAdd(&g_deg[dst], 1);
}

// segment offsets: warp scan + one atomic per warp (order-free, disjoint)
__global__ void k_off() {
    int n = blockIdx.x * blockDim.x + threadIdx.x;
    int lane = threadIdx.x & 31;
    int deg = (n < NENT) ? g_deg[n] : 0;
    int incl = deg;
#pragma unroll
    for (int o = 1; o < 32; o <<= 1) {
        int t = __shfl_up_sync(0xFFFFFFFFu, incl, o);
        if (lane >= o) incl += t;
    }
    int tot = __shfl_sync(0xFFFFFFFFu, incl, 31);
    int base = 0;
    if (lane == 31) base = atomicAdd(&g_total, tot);
    base = __shfl_sync(0xFFFFFFFFu, base, 31);
    if (n < NENT) {
        int st = base + incl - deg;
        g_off[n] = st;
        g_cur[n] = st;
    }
}

__global__ void k_scatter(const int* __restrict__ ei, const int* __restrict__ et) {
    int e = blockIdx.x * blockDim.x + threadIdx.x;
    if (e >= NEDGE) return;
    int src = clampi(ei[e], 0, NENT - 1);
    int dst = clampi(ei[NEDGE + e], 0, NENT - 1);
    int typ = clampi(et[e], 0, NREL - 1);
    int pos = atomicAdd(&g_cur[dst], 1);
    if (pos >= NEDGE) return;
    g_pk[pos] = src | (typ << 16);
}

// ---------------- aggregation: warp per node, local type-histogram -----------
__global__ __launch_bounds__(256)
void k_agg(const float* __restrict__ x, const float* __restrict__ comp) {
    __shared__ float comps[NREL * NB];
    __shared__ int   cnts[8][NREL];
    int tid = threadIdx.x;
    for (int t = tid; t < NREL * NB; t += 256) comps[t] = comp[t];
    __syncthreads();

    int w = tid >> 5, lane = tid & 31;
    int n = blockIdx.x * 8 + w;
    if (n >= NENT) return;

    for (int t = lane; t < NREL; t += 32) cnts[w][t] = 0;
    __syncwarp();
    int s = g_off[n], e = s + g_deg[n];
    for (int idx = s + lane; idx < e; idx += 32)
        atomicAdd(&cnts[w][(g_pk[idx] >> 16) & 0x3F], 1);
    __syncwarp();

    float4 av[NB];
#pragma unroll
    for (int b = 0; b < NB; b++) av[b] = make_float4(0.f, 0.f, 0.f, 0.f);

    for (int idx = s; idx < e; idx++) {
        int pk  = g_pk[idx];
        int src = pk & 0xFFFF;
        int typ = (pk >> 16) & 0x3F;
        float nm = 1.0f / (float)cnts[w][typ];
        float4 xv = *((const float4*)(x + (size_t)src * D) + lane);
#pragma unroll
        for (int b = 0; b < NB; b++) {
            float c = comps[typ * NB + b] * nm;
            av[b].x += c * xv.x; av[b].y += c * xv.y;
            av[b].z += c * xv.z; av[b].w += c * xv.w;
        }
    }

    size_t rb = (size_t)n * KTOT;
#pragma unroll
    for (int b = 0; b < NB; b++)
        *(float4*)(g_A + rb + b * D + lane * 4) = tf32r4(av[b]);
    float4 xv = *((const float4*)(x + (size_t)n * D) + lane);
    *(float4*)(g_A + rb + KACC + lane * 4) = tf32r4(xv);
}

// ---------------- B^T tf32: g_Bt[n][k] = [basis;root][k][n] ----------------
__global__ void k_prepB(const float* __restrict__ basis, const float* __restrict__ root) {
    int i = blockIdx.x * blockDim.x + threadIdx.x;
    if (i >= D * KTOT) return;
    int n = i / KTOT, k = i % KTOT;
    float v = (k < KACC) ? basis[(size_t)k * D + n] : root[(size_t)(k - KACC) * D + n];
    g_Bt[i] = tf32r(v);
}

// ---------------- tf32 HMMA GEMM, cp.async double-buffered -------------------
// CTA: 128x128 C tile, 8 warps = 2(m) x 4(n), each warp 64x32. KC=16, 2 stages.
__global__ __launch_bounds__(256)
void k_gemm(const float* __restrict__ bias, float* __restrict__ out) {
    __shared__ __align__(16) float sA[2][MTILE][SSTR];   // 20 KB
    __shared__ __align__(16) float sB[2][D][SSTR];       // 20 KB

    int tid = threadIdx.x, wid = tid >> 5, lane = tid & 31;
    int m0 = blockIdx.x * MTILE;
    int wm = wid & 1;          // m offset 64*wm
    int wn = wid >> 1;         // n offset 32*wn
    int grp = lane >> 2;       // fragment group row 0..7
    int tig = lane & 3;        // fragment col 0..3

    float c[4][4][4];
#pragma unroll
    for (int mt = 0; mt < 4; mt++)
#pragma unroll
        for (int nt = 0; nt < 4; nt++)
#pragma unroll
            for (int r = 0; r < 4; r++) c[mt][nt][r] = 0.f;

    // prologue: prefetch chunk 0 (each thread: 2 A-chunks + 2 B-chunks of 16B)
#pragma unroll
    for (int i = 0; i < 2; i++) {
        int cix = tid + i * 256;
        int r = cix >> 2, q = cix & 3;
        cp16(smem_u32(&sA[0][r][q * 4]), g_A + (size_t)(m0 + r) * KTOT + q * 4);
        cp16(smem_u32(&sB[0][r][q * 4]), g_Bt + (size_t)r * KTOT + q * 4);
    }
    cp_commit();

    for (int ch = 0; ch < NCH; ch++) {
        int st = ch & 1;
        if (ch + 1 < NCH) {
            int ns = (ch + 1) & 1;
            int kc = (ch + 1) * KC;
#pragma unroll
            for (int i = 0; i < 2; i++) {
                int cix = tid + i * 256;
                int r = cix >> 2, q = cix & 3;
                cp16(smem_u32(&sA[ns][r][q * 4]),
                     g_A + (size_t)(m0 + r) * KTOT + kc + q * 4);
                cp16(smem_u32(&sB[ns][r][q * 4]),
                     g_Bt + (size_t)r * KTOT + kc + q * 4);
            }
        }
        cp_commit();
        cp_wait<1>();
        __syncthreads();

#pragma unroll
        for (int ks = 0; ks < 2; ks++) {
            int k0 = ks * 8;
            uint32_t a[4][4], b[4][2];
#pragma unroll
            for (int mt = 0; mt < 4; mt++) {
                int r = wm * 64 + mt * 16 + grp;
                a[mt][0] = __float_as_uint(sA[st][r][k0 + tig]);
                a[mt][1] = __float_as_uint(sA[st][r + 8][k0 + tig]);
                a[mt][2] = __float_as_uint(sA[st][r][k0 + tig + 4]);
                a[mt][3] = __float_as_uint(sA[st][r + 8][k0 + tig + 4]);
            }
#pragma unroll
            for (int nt = 0; nt < 4; nt++) {
                int r = wn * 32 + nt * 8 + grp;
                b[nt][0] = __float_as_uint(sB[st][r][k0 + tig]);
                b[nt][1] = __float_as_uint(sB[st][r][k0 + tig + 4]);
            }
#pragma unroll
            for (int mt = 0; mt < 4; mt++)
#pragma unroll
                for (int nt = 0; nt < 4; nt++)
                    mma_tf32(c[mt][nt], a[mt], b[nt]);
        }
        __syncthreads();
    }

    // epilogue: frag (m16n8): lane owns rows grp, grp+8; cols tig*2, tig*2+1
#pragma unroll
    for (int mt = 0; mt < 4; mt++) {
#pragma unroll
        for (int nt = 0; nt < 4; nt++) {
            int m = m0 + wm * 64 + mt * 16 + grp;
            int n = wn * 32 + nt * 8 + tig * 2;
            float b0 = __ldg(bias + n), b1 = __ldg(bias + n + 1);
            if (m < NENT) {
                float2 v = make_float2(c[mt][nt][0] + b0, c[mt][nt][1] + b1);
                *(float2*)(out + (size_t)m * D + n) = v;
            }
            if (m + 8 < NENT) {
                float2 v = make_float2(c[mt][nt][2] + b0, c[mt][nt][3] + b1);
                *(float2*)(out + (size_t)(m + 8) * D + n) = v;
            }
        }
    }
}

// ---------------- special embedding concat ----------------
__global__ void k_special(const float* __restrict__ sp, float* __restrict__ out) {
    int i = blockIdx.x * blockDim.x + threadIdx.x;
    if (i < NSPEC * D) out[(size_t)NENT * D + i] = sp[i];
}

// ---------------- launch ----------------
extern "C" void kernel_launch(void* const* d_in, const int* in_sizes, int n_in,
                              void* d_out, int out_size) {
    const int*   ei    = (const int*)d_in[0];
    const int*   et    = (const int*)d_in[1];
    const float* x     = (const float*)d_in[2];
    const float* basis = (const float*)d_in[3];
    const float* comp  = (const float*)d_in[4];
    const float* root  = (const float*)d_in[5];
    const float* bias  = (const float*)d_in[6];
    const float* spec  = (const float*)d_in[7];
    float*       out   = (float*)d_out;

    k_zero<<<64, 256>>>();
    k_count<<<(NEDGE + 255) / 256, 256>>>(ei);
    k_off<<<(NENT + 255) / 256, 256>>>();
    k_scatter<<<(NEDGE + 255) / 256, 256>>>(ei, et);
    k_agg<<<(NENT + 7) / 8, 256>>>(x, comp);
    k_prepB<<<(D * KTOT + 255) / 256, 256>>>(basis, root);
    k_gemm<<<NTIL, 256>>>(bias, out);
    k_special<<<(NSPEC * D + 255) / 256, 256>>>(spec, out);
}

// round 8
// speedup vs baseline: 1.5675x; 1.3235x over previous
#include <cuda_runtime.h>
#include <cuda_fp16.h>
#include <cstdint>

#define D       128
#define NREL    48
#define NB      8
#define NENT    50000
#define NSPEC   64
#define NEDGE   600000
#define KACC    1024
#define KTOT    1152
#define MTILE   128
#define NTIL    391                 // ceil(50000/128)
#define MPAD    (NTIL * MTILE)      // 50048
#define KC      32
#define NCH     (KTOT / KC)         // 36
#define SSTR    40                  // smem row stride (halves): 80B, LDSM-validated

// ---------------- device scratch ----------------
__device__ int    g_deg[NENT];
__device__ int    g_off[NENT];
__device__ int    g_cur[NENT];
__device__ int    g_total;
__device__ int    g_pk[NEDGE];
__device__ __half g_xh[(size_t)NENT * D];      // x in fp16
__device__ __half g_A[(size_t)MPAD * KTOT];    // fp16 A; pad rows stay zero
__device__ __half g_Bh[(size_t)D * KTOT];      // B^T [n][k] fp16

__device__ __forceinline__ int clampi(int v, int lo, int hi) {
    return v < lo ? lo : (v > hi ? hi : v);
}
__device__ __forceinline__ uint32_t smem_u32(const void* p) {
    uint32_t a;
    asm("{ .reg .u64 t; cvta.to.shared.u64 t, %1; cvt.u32.u64 %0, t; }"
        : "=r"(a) : "l"(p));
    return a;
}
__device__ __forceinline__ void ldsm4(uint32_t* r, uint32_t addr) {
    asm volatile("ldmatrix.sync.aligned.m8n8.x4.shared.b16 {%0,%1,%2,%3}, [%4];"
        : "=r"(r[0]), "=r"(r[1]), "=r"(r[2]), "=r"(r[3]) : "r"(addr));
}
__device__ __forceinline__ void mma_f16(float* c, const uint32_t* a,
                                        const uint32_t* b) {
    asm volatile(
        "mma.sync.aligned.m16n8k16.row.col.f32.f16.f16.f32 "
        "{%0,%1,%2,%3}, {%4,%5,%6,%7}, {%8,%9}, {%0,%1,%2,%3};"
        : "+f"(c[0]), "+f"(c[1]), "+f"(c[2]), "+f"(c[3])
        : "r"(a[0]), "r"(a[1]), "r"(a[2]), "r"(a[3]), "r"(b[0]), "r"(b[1]));
}
__device__ __forceinline__ void cp16(uint32_t dst, const void* src) {
    asm volatile("cp.async.cg.shared.global [%0], [%1], 16;"
                 :: "r"(dst), "l"(src) : "memory");
}
__device__ __forceinline__ void cp_commit() {
    asm volatile("cp.async.commit_group;" ::: "memory");
}
template <int N>
__device__ __forceinline__ void cp_wait() {
    asm volatile("cp.async.wait_group %0;" :: "n"(N) : "memory");
}

// ---------------- preprocessing ----------------
__global__ void k_zero() {
    int total = NENT + 1;
    for (int i = blockIdx.x * blockDim.x + threadIdx.x; i < total;
         i += gridDim.x * blockDim.x) {
        if (i < NENT) g_deg[i] = 0;
        else          g_total = 0;
    }
}

__global__ void k_count(const int* __restrict__ ei) {
    int e = blockIdx.x * blockDim.x + threadIdx.x;
    if (e >= NEDGE) return;
    int dst = clampi(ei[NEDGE + e], 0, NENT - 1);
    atomicAdd(&g_deg[dst], 1);
}

__global__ void k_off() {
    int n = blockIdx.x * blockDim.x + threadIdx.x;
    int lane = threadIdx.x & 31;
    int deg = (n < NENT) ? g_deg[n] : 0;
    int incl = deg;
#pragma unroll
    for (int o = 1; o < 32; o <<= 1) {
        int t = __shfl_up_sync(0xFFFFFFFFu, incl, o);
        if (lane >= o) incl += t;
    }
    int tot = __shfl_sync(0xFFFFFFFFu, incl, 31);
    int base = 0;
    if (lane == 31) base = atomicAdd(&g_total, tot);
    base = __shfl_sync(0xFFFFFFFFu, base, 31);
    if (n < NENT) {
        int st = base + incl - deg;
        g_off[n] = st;
        g_cur[n] = st;
    }
}

__global__ void k_scatter(const int* __restrict__ ei, const int* __restrict__ et) {
    int e = blockIdx.x * blockDim.x + threadIdx.x;
    if (e >= NEDGE) return;
    int src = clampi(ei[e], 0, NENT - 1);
    int dst = clampi(ei[NEDGE + e], 0, NENT - 1);
    int typ = clampi(et[e], 0, NREL - 1);
    int pos = atomicAdd(&g_cur[dst], 1);
    if (pos >= NEDGE) return;
    g_pk[pos] = src | (typ << 16);
}

// ---------------- x -> fp16 ----------------
__global__ void k_prepX(const float* __restrict__ x) {
    int i = blockIdx.x * blockDim.x + threadIdx.x;   // i indexes pairs
    if (i >= NENT * D / 2) return;
    float2 v = *((const float2*)x + i);
    *((__half2*)g_xh + i) = __float22half2_rn(v);
}

// ---------------- aggregation: warp per node, fp16 gather, fp32 accum --------
__global__ __launch_bounds__(256)
void k_agg(const float* __restrict__ comp) {
    __shared__ float comps[NREL * NB];
    __shared__ int   cnts[8][NREL];
    int tid = threadIdx.x;
    for (int t = tid; t < NREL * NB; t += 256) comps[t] = comp[t];
    __syncthreads();

    int w = tid >> 5, lane = tid & 31;
    int n = blockIdx.x * 8 + w;
    if (n >= NENT) return;

    for (int t = lane; t < NREL; t += 32) cnts[w][t] = 0;
    __syncwarp();
    int s = g_off[n], e = s + g_deg[n];
    for (int idx = s + lane; idx < e; idx += 32)
        atomicAdd(&cnts[w][(g_pk[idx] >> 16) & 0x3F], 1);
    __syncwarp();

    float4 av[NB];
#pragma unroll
    for (int b = 0; b < NB; b++) av[b] = make_float4(0.f, 0.f, 0.f, 0.f);

    for (int idx = s; idx < e; idx++) {
        int pk  = g_pk[idx];
        int src = pk & 0xFFFF;
        int typ = (pk >> 16) & 0x3F;
        float nm = 1.0f / (float)cnts[w][typ];
        // 4 halves per lane (8B): columns lane*4 .. lane*4+3
        uint2 u = *(const uint2*)(g_xh + (size_t)src * D + lane * 4);
        float2 x01 = __half22float2(*(__half2*)&u.x);
        float2 x23 = __half22float2(*(__half2*)&u.y);
#pragma unroll
        for (int b = 0; b < NB; b++) {
            float c = comps[typ * NB + b] * nm;
            av[b].x += c * x01.x; av[b].y += c * x01.y;
            av[b].z += c * x23.x; av[b].w += c * x23.y;
        }
    }

    size_t rb = (size_t)n * KTOT;
#pragma unroll
    for (int b = 0; b < NB; b++) {
        uint2 u;
        *(__half2*)&u.x = __float22half2_rn(make_float2(av[b].x, av[b].y));
        *(__half2*)&u.y = __float22half2_rn(make_float2(av[b].z, av[b].w));
        *(uint2*)(g_A + rb + b * D + lane * 4) = u;
    }
    // x tail (root part): already fp16
    *(uint2*)(g_A + rb + KACC + lane * 4) =
        *(const uint2*)(g_xh + (size_t)n * D + lane * 4);
}

// ---------------- B^T fp16: g_Bh[n][k] = [basis;root][k][n] ----------------
__global__ void k_prepB(const float* __restrict__ basis, const float* __restrict__ root) {
    int i = blockIdx.x * blockDim.x + threadIdx.x;
    if (i >= D * KTOT) return;
    int n = i / KTOT, k = i % KTOT;
    float v = (k < KACC) ? basis[(size_t)k * D + n] : root[(size_t)(k - KACC) * D + n];
    g_Bh[i] = __float2half_rn(v);
}

// ---------------- fp16 HMMA GEMM, cp.async double-buffered -------------------
// CTA: 128x128 C tile, 8 warps = 2(m) x 4(n), each warp 64x32. KC=32, 2 stages.
__global__ __launch_bounds__(256)
void k_gemm(const float* __restrict__ bias, float* __restrict__ out) {
    __shared__ __align__(16) __half sA[2][MTILE][SSTR];   // 20 KB
    __shared__ __align__(16) __half sB[2][D][SSTR];       // 20 KB

    int tid = threadIdx.x, wid = tid >> 5, lane = tid & 31;
    int m0 = blockIdx.x * MTILE;
    int wm = wid & 1;
    int wn = wid >> 1;

    float c[4][4][4];
#pragma unroll
    for (int mt = 0; mt < 4; mt++)
#pragma unroll
        for (int nt = 0; nt < 4; nt++)
#pragma unroll
            for (int r = 0; r < 4; r++) c[mt][nt][r] = 0.f;

    // prefetch chunk 0: per array 128 rows x 32 halves = 4 x 16B per row
#pragma unroll
    for (int i = 0; i < 2; i++) {
        int cix = tid + i * 256;
        int r = cix >> 2, q = cix & 3;
        cp16(smem_u32(&sA[0][r][q * 8]), g_A + (size_t)(m0 + r) * KTOT + q * 8);
        cp16(smem_u32(&sB[0][r][q * 8]), g_Bh + (size_t)r * KTOT + q * 8);
    }
    cp_commit();

    for (int ch = 0; ch < NCH; ch++) {
        int st = ch & 1;
        if (ch + 1 < NCH) {
            int ns = (ch + 1) & 1;
            int kc = (ch + 1) * KC;
#pragma unroll
            for (int i = 0; i < 2; i++) {
                int cix = tid + i * 256;
                int r = cix >> 2, q = cix & 3;
                cp16(smem_u32(&sA[ns][r][q * 8]),
                     g_A + (size_t)(m0 + r) * KTOT + kc + q * 8);
                cp16(smem_u32(&sB[ns][r][q * 8]),
                     g_Bh + (size_t)r * KTOT + kc + q * 8);
            }
        }
        cp_commit();
        cp_wait<1>();
        __syncthreads();

#pragma unroll
        for (int ks = 0; ks < 2; ks++) {
            uint32_t a[4][4], b[2][4];
            int arow = wm * 64 + (lane & 15);
            int acol = ks * 16 + (lane >> 4) * 8;
#pragma unroll
            for (int mt = 0; mt < 4; mt++)
                ldsm4(a[mt], smem_u32(&sA[st][arow + mt * 16][acol]));
            int brow = wn * 32 + (lane & 7) + ((lane >> 4) << 3);
            int bcol = ks * 16 + ((lane >> 3) & 1) * 8;
#pragma unroll
            for (int p = 0; p < 2; p++)
                ldsm4(b[p], smem_u32(&sB[st][brow + p * 16][bcol]));
#pragma unroll
            for (int mt = 0; mt < 4; mt++)
#pragma unroll
                for (int nt = 0; nt < 4; nt++)
                    mma_f16(c[mt][nt], a[mt], &b[nt >> 1][(nt & 1) * 2]);
        }
        __syncthreads();
    }

    // epilogue: frag (m16n8): lane owns rows l/4, l/4+8; cols (l&3)*2, +1
#pragma unroll
    for (int mt = 0; mt < 4; mt++) {
#pragma unroll
        for (int nt = 0; nt < 4; nt++) {
            int m = m0 + wm * 64 + mt * 16 + (lane >> 2);
            int n = wn * 32 + nt * 8 + (lane & 3) * 2;
            float b0 = __ldg(bias + n), b1 = __ldg(bias + n + 1);
            if (m < NENT) {
                float2 v = make_float2(c[mt][nt][0] + b0, c[mt][nt][1] + b1);
                *(float2*)(out + (size_t)m * D + n) = v;
            }
            if (m + 8 < NENT) {
                float2 v = make_float2(c[mt][nt][2] + b0, c[mt][nt][3] + b1);
                *(float2*)(out + (size_t)(m + 8) * D + n) = v;
            }
        }
    }
}

// ---------------- special embedding concat ----------------
__global__ void k_special(const float* __restrict__ sp, float* __restrict__ out) {
    int i = blockIdx.x * blockDim.x + threadIdx.x;
    if (i < NSPEC * D) out[(size_t)NENT * D + i] = sp[i];
}

// ---------------- launch ----------------
extern "C" void kernel_launch(void* const* d_in, const int* in_sizes, int n_in,
                              void* d_out, int out_size) {
    const int*   ei    = (const int*)d_in[0];
    const int*   et    = (const int*)d_in[1];
    const float* x     = (const float*)d_in[2];
    const float* basis = (const float*)d_in[3];
    const float* comp  = (const float*)d_in[4];
    const float* root  = (const float*)d_in[5];
    const float* bias  = (const float*)d_in[6];
    const float* spec  = (const float*)d_in[7];
    float*       out   = (float*)d_out;

    k_zero<<<64, 256>>>();
    k_count<<<(NEDGE + 255) / 256, 256>>>(ei);
    k_off<<<(NENT + 255) / 256, 256>>>();
    k_scatter<<<(NEDGE + 255) / 256, 256>>>(ei, et);
    k_prepX<<<(NENT * D / 2 + 255) / 256, 256>>>(x);
    k_agg<<<(NENT + 7) / 8, 256>>>(comp);
    k_prepB<<<(D * KTOT + 255) / 256, 256>>>(basis, root);
    k_gemm<<<NTIL, 256>>>(bias, out);
    k_special<<<(NSPEC * D + 255) / 256, 256>>>(spec, out);
}